// round 12
// baseline (speedup 1.0000x reference)
#include <cuda_runtime.h>
#include <cuda_fp16.h>
#include <stdint.h>

#define NN 100000
#define NE 3200000
#define NG 1000
#define SLOT 128                    // padded per-node capacity (P(deg>128) ~ e^-80)

// ---------------- scratch (module-load device globals, allowed) ----------------
__device__ float  g_deg[NN];
__device__ float  g_dinv[NN];
__device__ int    g_cnt[NN];
__device__ int2   g_csrp[NN * SLOT];  // padded CSR: {src, weight bits} at node*SLOT+rank
__device__ float4 g_x4[NN];           // x padded; after k_dinv: premultiplied by dinv
__device__ __half g_a1h[NN * 16];     // dinv * relu(layer1 out), fp16 (32B rows)
__device__ float  g_pool[NG * 16];
__device__ int    g_is64;             // 1 if integer inputs are int64, 0 if int32

// ---------------- kernels ----------------

// Init + dtype detect fused. Block 0 probes the first 4096 odd int32 words:
// int64 node ids (< 1e5) have zero high words; int32 data has ids there.
__global__ void __launch_bounds__(256) k_init(const float* __restrict__ x,
                                              const int* __restrict__ ei32) {
    int i = blockIdx.x * blockDim.x + threadIdx.x;
    if (i < NN) {
        g_cnt[i] = 0;
        g_deg[i] = 0.0f;
        g_x4[i] = make_float4(x[3 * i], x[3 * i + 1], x[3 * i + 2], 0.0f);
    }
    if (i < NG * 16) g_pool[i] = 0.0f;
    if (blockIdx.x == 0) {
        int nz = 0;
        for (int p = threadIdx.x; p < 4096; p += 256) nz |= ei32[2 * p + 1];
        int any = __syncthreads_or(nz != 0);
        if (threadIdx.x == 0) g_is64 = any ? 0 : 1;
    }
}

// Pad launches: position k_build at the ncu-profiled launch index.
__global__ void k_padA() {}
__global__ void k_padB() {}

// Single edge pass: returning atomic gives the rank (padded-slot address);
// fire-and-forget REDG accumulates weighted degree in the same pass.
__global__ void __launch_bounds__(256) k_build(const void* __restrict__ ei,
                                               const float* __restrict__ ew) {
    int is64 = g_is64;
    int e = blockIdx.x * blockDim.x + threadIdx.x;
    if (e >= NE) return;
    int r, c;
    if (is64) {
        r = (int)((const long long*)ei)[e];
        c = (int)((const long long*)ei)[NE + e];
    } else {
        r = ((const int*)ei)[e];
        c = ((const int*)ei)[NE + e];
    }
    float w = ew[e];
    int rank = atomicAdd(&g_cnt[c], 1);
    atomicAdd(&g_deg[c], w);                 // return discarded -> REDG
    g_csrp[c * SLOT + rank] = make_int2(r, __float_as_int(w));
}

// Elementwise: dinv = rsqrt(deg + 1); premultiply x4 by dinv.
__global__ void __launch_bounds__(256) k_dinv() {
    int i = blockIdx.x * blockDim.x + threadIdx.x;
    if (i >= NN) return;
    float di = rsqrtf(g_deg[i] + 1.0f);      // + self-loop weight
    g_dinv[i] = di;
    float4 v = g_x4[i];
    v.x *= di; v.y *= di; v.z *= di;
    g_x4[i] = v;                             // x4 is now dinv[i]*x[i]
}

// Layer 1: 4 nodes per warp, 8 lanes per node. s = sum(w * x4p[r]);
// agg = dinv[c]*(s + x4p[c]); each lane computes 2 of 16 outputs of
// relu(agg@W1+b1), stores dinv[c]*h as one half2 (warp writes 128B contiguous).
__global__ void __launch_bounds__(256) k_layer1(const float* __restrict__ W1,
                                                const float* __restrict__ b1) {
    int wid = (blockIdx.x * blockDim.x + threadIdx.x) >> 5;
    int lane = threadIdx.x & 31;
    int grp = lane >> 3;                     // 0..3 -> node within warp
    int lg  = lane & 7;                      // lane within group
    int node = wid * 4 + grp;
    bool valid = node < NN;
    int base = valid ? node * SLOT : 0;
    int n = valid ? g_cnt[node] : 0;
    float s0 = 0.f, s1 = 0.f, s2 = 0.f;
    for (int e = base + lg; e < base + n; e += 8) {
        int2 p = g_csrp[e];
        float w = __int_as_float(p.y);
        float4 xr = g_x4[p.x];               // premultiplied; one LDG.128
        s0 += w * xr.x;
        s1 += w * xr.y;
        s2 += w * xr.z;
    }
#pragma unroll
    for (int off = 1; off < 8; off <<= 1) {  // reduce within 8-lane group
        s0 += __shfl_xor_sync(0xffffffffu, s0, off);
        s1 += __shfl_xor_sync(0xffffffffu, s1, off);
        s2 += __shfl_xor_sync(0xffffffffu, s2, off);
    }
    float di = valid ? g_dinv[node] : 0.0f;
    float4 xs = valid ? g_x4[node] : make_float4(0.f, 0.f, 0.f, 0.f);
    s0 = di * (s0 + xs.x);
    s1 = di * (s1 + xs.y);
    s2 = di * (s2 + xs.z);
    int f0 = 2 * lg, f1 = f0 + 1;
    float o0 = b1[f0] + s0 * W1[f0] + s1 * W1[16 + f0] + s2 * W1[32 + f0];
    float o1 = b1[f1] + s0 * W1[f1] + s1 * W1[16 + f1] + s2 * W1[32 + f1];
    if (valid) {
        ((__half2*)g_a1h)[node * 8 + lg] =
            __floats2half2_rn(di * fmaxf(o0, 0.0f), di * fmaxf(o1, 0.0f));
    }
}

// Layer 2: warp/node, 4 groups x 8 lanes, half2 per lane. Pool is aggregated
// in smem first (batch is sorted -> a block's 8 nodes span 1-2 graphs almost
// always; 8 smem slots + direct-global fallback), then flushed: ~0.2M global
// REDG instead of 1.6M.
__global__ void __launch_bounds__(256) k_layer2(const float* __restrict__ W2,
                                                const float* __restrict__ b2,
                                                const void* __restrict__ batch) {
    __shared__ float spool[8][16];
    __shared__ int s_g0;
    int is64 = g_is64;
    int tid = threadIdx.x;
    int wid = (blockIdx.x * blockDim.x + tid) >> 5;   // == node (grid exact)
    int lane = tid & 31;
    if (tid < 128) ((float*)spool)[tid] = 0.0f;
    if (tid == 0) {
        int n0 = blockIdx.x * 8;
        s_g0 = is64 ? (int)((const long long*)batch)[n0]
                    : ((const int*)batch)[n0];
    }
    __syncthreads();

    const __half2* a1h2 = (const __half2*)g_a1h;
    int grp = lane >> 3;                     // 0..3
    int ff  = lane & 7;                      // feature pair index
    int base = wid * SLOT;
    int end = base + g_cnt[wid];
    float ax = 0.0f, ay = 0.0f;
    for (int e = base + grp; e < end; e += 4) {
        int2 p = g_csrp[e];                  // broadcast within group
        float w = __int_as_float(p.y);
        float2 v = __half22float2(a1h2[p.x * 8 + ff]);
        ax += w * v.x;
        ay += w * v.y;
    }
#pragma unroll
    for (int off = 8; off <= 16; off <<= 1) {
        ax += __shfl_xor_sync(0xffffffffu, ax, off);
        ay += __shfl_xor_sync(0xffffffffu, ay, off);
    }
    float di = g_dinv[wid];
    float2 vs = __half22float2(a1h2[wid * 8 + ff]);  // premultiplied self
    ax = di * (ax + vs.x);
    ay = di * (ay + vs.y);
    int f = lane & 15;
    float o = b2[f];
#pragma unroll
    for (int k = 0; k < 16; k++) {
        float vk = __shfl_sync(0xffffffffu, (k & 1) ? ay : ax, k >> 1);
        o += vk * W2[k * 16 + f];
    }
    o = fmaxf(o, 0.0f);
    if (lane < 16) {
        int g = is64 ? (int)((const long long*)batch)[wid]
                     : ((const int*)batch)[wid];
        int dg = g - s_g0;
        if (dg < 8) atomicAdd(&spool[dg][f], o);     // smem aggregation
        else        atomicAdd(&g_pool[g * 16 + f], o); // rare fallback
    }
    __syncthreads();
    if (tid < 128) {
        float v = ((float*)spool)[tid];
        if (v != 0.0f) atomicAdd(&g_pool[(s_g0 + (tid >> 4)) * 16 + (tid & 15)], v);
    }
}

__global__ void __launch_bounds__(256) k_final(const float* __restrict__ Wlin,
                                               const float* __restrict__ blin,
                                               float* __restrict__ out) {
    int t = blockIdx.x * blockDim.x + threadIdx.x;
    if (t >= NG * 7) return;
    int g = t / 7, j = t % 7;
    float o = blin[j];
#pragma unroll
    for (int k = 0; k < 16; k++) o += g_pool[g * 16 + k] * Wlin[k * 7 + j];
    out[t] = o;
}

// ---------------- launch ----------------

extern "C" void kernel_launch(void* const* d_in, const int* in_sizes, int n_in,
                              void* d_out, int out_size) {
    const float* x     = (const float*)d_in[0];
    const void*  ei    = d_in[1];
    const float* ew    = (const float*)d_in[2];
    const void*  batch = d_in[3];
    const float* W1    = (const float*)d_in[4];
    const float* b1    = (const float*)d_in[5];
    const float* W2    = (const float*)d_in[6];
    const float* b2    = (const float*)d_in[7];
    const float* Wlin  = (const float*)d_in[8];
    const float* blin  = (const float*)d_in[9];
    float* out = (float*)d_out;

    k_init   <<<(NN + 255) / 256, 256>>>(x, (const int*)ei);  // 0
    k_padA   <<<1, 32>>>();                                   // 1
    k_padB   <<<1, 32>>>();                                   // 2
    k_build  <<<(NE + 255) / 256, 256>>>(ei, ew);             // 3 (profiled)
    k_dinv   <<<(NN + 255) / 256, 256>>>();                   // 4
    k_layer1 <<<(NN / 4 * 32 + 255) / 256, 256>>>(W1, b1);    // 5
    k_layer2 <<<(NN * 32 + 255) / 256, 256>>>(W2, b2, batch); // 6
    k_final  <<<(NG * 7 + 255) / 256, 256>>>(Wlin, blin, out);// 7
}

// round 13
// speedup vs baseline: 1.1081x; 1.1081x over previous
#include <cuda_runtime.h>
#include <cuda_fp16.h>
#include <stdint.h>

#define NN 100000
#define NE 3200000
#define NG 1000
#define SLOT 128                    // padded per-node capacity (P(deg>128) ~ e^-80)

// ---------------- scratch (module-load device globals, allowed) ----------------
__device__ float  g_dinv[NN];
__device__ int    g_cnt[NN];
__device__ int2   g_csrp[NN * SLOT];  // padded CSR: {src, weight bits} at node*SLOT+rank
__device__ float4 g_x4[NN];           // x padded; after k_deg: premultiplied by dinv
__device__ __half g_a1h[NN * 16];     // dinv * relu(layer1 out), fp16 (32B rows)
__device__ float  g_pool[NG * 16];
__device__ int    g_is64;             // 1 if integer inputs are int64, 0 if int32

// ---------------- kernels ----------------

// Init + dtype detect fused. Block 0 probes the first 4096 odd int32 words:
// int64 node ids (< 1e5) have zero high words; int32 data has ids there.
__global__ void __launch_bounds__(256) k_init(const float* __restrict__ x,
                                              const int* __restrict__ ei32) {
    int i = blockIdx.x * blockDim.x + threadIdx.x;
    if (i < NN) {
        g_cnt[i] = 0;
        g_x4[i] = make_float4(x[3 * i], x[3 * i + 1], x[3 * i + 2], 0.0f);
    }
    if (i < NG * 16) g_pool[i] = 0.0f;
    if (blockIdx.x == 0) {
        int nz = 0;
        for (int p = threadIdx.x; p < 4096; p += 256) nz |= ei32[2 * p + 1];
        int any = __syncthreads_or(nz != 0);
        if (threadIdx.x == 0) g_is64 = any ? 0 : 1;
    }
}

// Single edge pass: returning atomic gives the rank (padded-slot address).
// Deg moved OUT of this kernel: it was ~13us of extra LTS-atomic pressure here;
// it's an atomic-free coalesced pass afterwards (k_deg).
__global__ void __launch_bounds__(256) k_build(const void* __restrict__ ei,
                                               const float* __restrict__ ew) {
    int is64 = g_is64;
    int e = blockIdx.x * blockDim.x + threadIdx.x;
    if (e >= NE) return;
    int r, c;
    if (is64) {
        r = (int)((const long long*)ei)[e];
        c = (int)((const long long*)ei)[NE + e];
    } else {
        r = ((const int*)ei)[e];
        c = ((const int*)ei)[NE + e];
    }
    int rank = atomicAdd(&g_cnt[c], 1);
    g_csrp[c * SLOT + rank] = make_int2(r, __float_as_int(ew[e]));
}

// Coalesced segment sum of weights -> dinv; premultiply x4 by dinv.
// 4 nodes per warp, 8 lanes per node.
__global__ void __launch_bounds__(256) k_deg() {
    int wid = (blockIdx.x * blockDim.x + threadIdx.x) >> 5;
    int lane = threadIdx.x & 31;
    int node = wid * 4 + (lane >> 3);
    int lg = lane & 7;
    bool valid = node < NN;
    int base = valid ? node * SLOT : 0;
    int n = valid ? g_cnt[node] : 0;
    float s = 0.0f;
    for (int e = base + lg; e < base + n; e += 8)
        s += __int_as_float(g_csrp[e].y);
#pragma unroll
    for (int off = 1; off < 8; off <<= 1)
        s += __shfl_xor_sync(0xffffffffu, s, off);
    if (valid && lg == 0) {
        float di = rsqrtf(s + 1.0f);         // + self-loop weight
        g_dinv[node] = di;
        float4 v = g_x4[node];
        v.x *= di; v.y *= di; v.z *= di;
        g_x4[node] = v;                      // x4 is now dinv[i]*x[i]
    }
}

// Layer 1: 4 nodes per warp, 8 lanes per node. s = sum(w * x4p[r]);
// agg = dinv[c]*(s + x4p[c]); each lane computes 2 of 16 outputs of
// relu(agg@W1+b1), stores dinv[c]*h as one half2 (warp writes 128B contiguous).
__global__ void __launch_bounds__(256) k_layer1(const float* __restrict__ W1,
                                                const float* __restrict__ b1) {
    int wid = (blockIdx.x * blockDim.x + threadIdx.x) >> 5;
    int lane = threadIdx.x & 31;
    int grp = lane >> 3;                     // 0..3 -> node within warp
    int lg  = lane & 7;                      // lane within group
    int node = wid * 4 + grp;
    bool valid = node < NN;
    int base = valid ? node * SLOT : 0;
    int n = valid ? g_cnt[node] : 0;
    float s0 = 0.f, s1 = 0.f, s2 = 0.f;
    for (int e = base + lg; e < base + n; e += 8) {
        int2 p = g_csrp[e];
        float w = __int_as_float(p.y);
        float4 xr = g_x4[p.x];               // premultiplied; one LDG.128
        s0 += w * xr.x;
        s1 += w * xr.y;
        s2 += w * xr.z;
    }
#pragma unroll
    for (int off = 1; off < 8; off <<= 1) {  // reduce within 8-lane group
        s0 += __shfl_xor_sync(0xffffffffu, s0, off);
        s1 += __shfl_xor_sync(0xffffffffu, s1, off);
        s2 += __shfl_xor_sync(0xffffffffu, s2, off);
    }
    float di = valid ? g_dinv[node] : 0.0f;
    float4 xs = valid ? g_x4[node] : make_float4(0.f, 0.f, 0.f, 0.f);
    s0 = di * (s0 + xs.x);
    s1 = di * (s1 + xs.y);
    s2 = di * (s2 + xs.z);
    int f0 = 2 * lg, f1 = f0 + 1;
    float o0 = b1[f0] + s0 * W1[f0] + s1 * W1[16 + f0] + s2 * W1[32 + f0];
    float o1 = b1[f1] + s0 * W1[f1] + s1 * W1[16 + f1] + s2 * W1[32 + f1];
    if (valid) {
        ((__half2*)g_a1h)[node * 8 + lg] =
            __floats2half2_rn(di * fmaxf(o0, 0.0f), di * fmaxf(o1, 0.0f));
    }
}

// Layer 2: warp/node, 4 groups x 8 lanes, half2 per lane;
// agg = dinv[c]*(sum w*a1p[r] + a1p[c]); out = relu(agg@W2+b2); REDG pool.
__global__ void __launch_bounds__(256) k_layer2(const float* __restrict__ W2,
                                                const float* __restrict__ b2,
                                                const void* __restrict__ batch) {
    int is64 = g_is64;
    int wid = (blockIdx.x * blockDim.x + threadIdx.x) >> 5;
    int lane = threadIdx.x & 31;
    if (wid >= NN) return;
    const __half2* a1h2 = (const __half2*)g_a1h;
    int grp = lane >> 3;                     // 0..3
    int ff  = lane & 7;                      // feature pair index
    int base = wid * SLOT;
    int end = base + g_cnt[wid];
    float ax = 0.0f, ay = 0.0f;
    for (int e = base + grp; e < end; e += 4) {
        int2 p = g_csrp[e];                  // broadcast within group
        float w = __int_as_float(p.y);
        float2 v = __half22float2(a1h2[p.x * 8 + ff]);
        ax += w * v.x;
        ay += w * v.y;
    }
#pragma unroll
    for (int off = 8; off <= 16; off <<= 1) {
        ax += __shfl_xor_sync(0xffffffffu, ax, off);
        ay += __shfl_xor_sync(0xffffffffu, ay, off);
    }
    float di = g_dinv[wid];
    float2 vs = __half22float2(a1h2[wid * 8 + ff]);  // premultiplied self
    ax = di * (ax + vs.x);
    ay = di * (ay + vs.y);
    int f = lane & 15;
    float o = b2[f];
#pragma unroll
    for (int k = 0; k < 16; k++) {
        float vk = __shfl_sync(0xffffffffu, (k & 1) ? ay : ax, k >> 1);
        o += vk * W2[k * 16 + f];
    }
    o = fmaxf(o, 0.0f);
    if (lane < 16) {
        int g = is64 ? (int)((const long long*)batch)[wid]
                     : ((const int*)batch)[wid];
        atomicAdd(&g_pool[g * 16 + f], o);
    }
}

__global__ void __launch_bounds__(256) k_final(const float* __restrict__ Wlin,
                                               const float* __restrict__ blin,
                                               float* __restrict__ out) {
    int t = blockIdx.x * blockDim.x + threadIdx.x;
    if (t >= NG * 7) return;
    int g = t / 7, j = t % 7;
    float o = blin[j];
#pragma unroll
    for (int k = 0; k < 16; k++) o += g_pool[g * 16 + k] * Wlin[k * 7 + j];
    out[t] = o;
}

// ---------------- launch ----------------

extern "C" void kernel_launch(void* const* d_in, const int* in_sizes, int n_in,
                              void* d_out, int out_size) {
    const float* x     = (const float*)d_in[0];
    const void*  ei    = d_in[1];
    const float* ew    = (const float*)d_in[2];
    const void*  batch = d_in[3];
    const float* W1    = (const float*)d_in[4];
    const float* b1    = (const float*)d_in[5];
    const float* W2    = (const float*)d_in[6];
    const float* b2    = (const float*)d_in[7];
    const float* Wlin  = (const float*)d_in[8];
    const float* blin  = (const float*)d_in[9];
    float* out = (float*)d_out;

    k_init   <<<(NN + 255) / 256, 256>>>(x, (const int*)ei);  // 0
    k_build  <<<(NE + 255) / 256, 256>>>(ei, ew);             // 1
    k_deg    <<<(NN / 4 * 32 + 255) / 256, 256>>>();          // 2
    k_layer1 <<<(NN / 4 * 32 + 255) / 256, 256>>>(W1, b1);    // 3 (profiled)
    k_layer2 <<<(NN * 32 + 255) / 256, 256>>>(W2, b2, batch); // 4
    k_final  <<<(NG * 7 + 255) / 256, 256>>>(Wlin, blin, out);// 5
}